// round 13
// baseline (speedup 1.0000x reference)
#include <cuda_runtime.h>
#include <cuda_bf16.h>
#include <cstdint>

#define N_VOX 200000
#define PP    65536
#define EPSV  1e-5f
#define TILES 8

// ---- scratch (__device__ globals; allocation-free rule) ----
__device__ float g_h1[(size_t)N_VOX * 64];
__device__ float g_h2[(size_t)N_VOX * 64];
__device__ __nv_bfloat16 g_wb[27 * 9216];  // [27][hi 64x72 | lo 64x72] bf16 row-major [k][n]
__device__ float g_stats[256];
__device__ float g_coef[256];

#define RED2(p, a, b) \
    asm volatile("red.global.add.v2.f32 [%0], {%1,%2};" \
                 :: "l"(p), "f"(a), "f"(b) : "memory")

#define LDMA4(r, addr) \
    asm volatile("ldmatrix.sync.aligned.m8n8.x4.shared.b16 {%0,%1,%2,%3}, [%4];" \
                 : "=r"((r)[0]), "=r"((r)[1]), "=r"((r)[2]), "=r"((r)[3]) : "r"(addr))

// x4.trans: lanes 0-15 address hi tiles, lanes 16-31 address lo tiles
#define LDMB4T(r, addr) \
    asm volatile("ldmatrix.sync.aligned.m8n8.x4.trans.shared.b16 {%0,%1,%2,%3}, [%4];" \
                 : "=r"((r)[0]), "=r"((r)[1]), "=r"((r)[2]), "=r"((r)[3]) : "r"(addr))

#define MMA16816(d, a, b) \
    asm volatile("mma.sync.aligned.m16n8k16.row.col.f32.bf16.bf16.f32 " \
                 "{%0,%1,%2,%3},{%4,%5,%6,%7},{%8,%9},{%0,%1,%2,%3};" \
                 : "+f"((d)[0]), "+f"((d)[1]), "+f"((d)[2]), "+f"((d)[3]) \
                 : "r"((a)[0]), "r"((a)[1]), "r"((a)[2]), "r"((a)[3]), \
                   "r"((b)[0]), "r"((b)[1]))

// smem layout (bytes):
//   [0, 36864): four 9216B warp chunks: sAh bf16[32][72] @ +0, sAl @ +4608
//   [36864, 55296): sW bf16 [hi 64x72 | lo 64x72], row-major [k][n], staged once
#define WCHUNK 9216
#define DSMEM_BYTES 55296

// ---------------------------------------------------------------------------
template <bool SCATTER, bool FUSE_BN>
__global__ __launch_bounds__(128, 4)
void conv_mma_kernel(const float* __restrict__ x,
                     const __nv_bfloat16* __restrict__ wb,
                     const int* __restrict__ in_map,
                     const int* __restrict__ out_map,
                     float* __restrict__ H)
{
    extern __shared__ char sm[];

    const int t    = threadIdx.x;
    const int w    = t >> 5;
    const int lane = t & 31;

    __nv_bfloat16* sAh = reinterpret_cast<__nv_bfloat16*>(sm + w * WCHUNK);
    __nv_bfloat16* sAl = sAh + 32 * 72;

    const int ky = SCATTER ? blockIdx.y : 0;
    const int o  = SCATTER ? (ky < 13 ? ky : ky + 1) : 13;

    // Stage W_o once per block (hi+lo, stride 72 = 144B rows, 18432 B)
    {
        const uint4* src = reinterpret_cast<const uint4*>(wb + (size_t)o * 9216);
        uint4*       dst = reinterpret_cast<uint4*>(sm + 36864);
#pragma unroll
        for (int i = 0; i < 9; i++) dst[t + i * 128] = src[t + i * 128];
    }
    __syncthreads();   // only block barrier

    const uint32_t aAh = (uint32_t)__cvta_generic_to_shared(sAh);
    const uint32_t aAl = (uint32_t)__cvta_generic_to_shared(sAl);
    const uint32_t aW  = (uint32_t)__cvta_generic_to_shared(sm + 36864);

    // gather mapping: 8 lanes per row -> 4 rows per warp instruction
    const int rsub = lane >> 3;       // 0..3
    const int c8   = lane & 7;        // 8-float column group

    float4 sc0, sc1, sb0, sb1;
    if (FUSE_BN) {
        sc0 = *reinterpret_cast<const float4*>(&g_coef[c8 * 8]);
        sc1 = *reinterpret_cast<const float4*>(&g_coef[c8 * 8 + 4]);
        sb0 = *reinterpret_cast<const float4*>(&g_coef[64 + c8 * 8]);
        sb1 = *reinterpret_cast<const float4*>(&g_coef[64 + c8 * 8 + 4]);
    }

    // ---- pipelined map load: tile 0's maps loaded before the loop ----
    int myrow = 0, myorow = 0, tfirst = 0;
    if (SCATTER) {
        const size_t kb0 = (size_t)ky * PP + (size_t)blockIdx.x * TILES * 128;
        tfirst = __ldg(&in_map[kb0]);
        myrow  = __ldg(&in_map[kb0 + t]);
        myorow = __ldg(&out_map[kb0 + t]);
    }

    for (int tt = 0; tt < TILES; tt++) {
        const int base = (blockIdx.x * TILES + tt) * 128;
        if (!SCATTER && base >= N_VOX) break;
        if (SCATTER && tfirst >= N_VOX) break;   // tail-packed sentinels

        // prefetch next tile's maps NOW (consumed next iteration)
        int nrow = 0, norow = 0, nfirst = N_VOX;
        if (SCATTER && tt + 1 < TILES) {
            const size_t kbn = (size_t)ky * PP + (size_t)(base + 128);
            nfirst = __ldg(&in_map[kbn]);
            nrow   = __ldg(&in_map[kbn + t]);
            norow  = __ldg(&out_map[kbn + t]);
        }

        // ---- Gather (+ fused BN1+ReLU) + bf16 hi/lo split, STS.128 ----
        {
            const float4* x4 = reinterpret_cast<const float4*>(x);
#pragma unroll
            for (int j = 0; j < 8; j++) {
                const int rl  = j * 4 + rsub;     // local row 0..31
                const int row = SCATTER ? __shfl_sync(0xffffffffu, myrow, rl)
                                        : (base + w * 32 + rl);
                float4 v0 = make_float4(0.f, 0.f, 0.f, 0.f), v1 = v0;
                if (row < N_VOX) {
                    v0 = x4[(size_t)row * 16 + c8 * 2];
                    v1 = x4[(size_t)row * 16 + c8 * 2 + 1];
                }
                if (FUSE_BN) {
                    v0.x = fmaxf(fmaf(v0.x, sc0.x, sb0.x), 0.f);
                    v0.y = fmaxf(fmaf(v0.y, sc0.y, sb0.y), 0.f);
                    v0.z = fmaxf(fmaf(v0.z, sc0.z, sb0.z), 0.f);
                    v0.w = fmaxf(fmaf(v0.w, sc0.w, sb0.w), 0.f);
                    v1.x = fmaxf(fmaf(v1.x, sc1.x, sb1.x), 0.f);
                    v1.y = fmaxf(fmaf(v1.y, sc1.y, sb1.y), 0.f);
                    v1.z = fmaxf(fmaf(v1.z, sc1.z, sb1.z), 0.f);
                    v1.w = fmaxf(fmaf(v1.w, sc1.w, sb1.w), 0.f);
                }
                union { __nv_bfloat16 b[8]; uint4 u; } hi, lo;
                hi.b[0] = __float2bfloat16(v0.x); hi.b[1] = __float2bfloat16(v0.y);
                hi.b[2] = __float2bfloat16(v0.z); hi.b[3] = __float2bfloat16(v0.w);
                hi.b[4] = __float2bfloat16(v1.x); hi.b[5] = __float2bfloat16(v1.y);
                hi.b[6] = __float2bfloat16(v1.z); hi.b[7] = __float2bfloat16(v1.w);
                lo.b[0] = __float2bfloat16(v0.x - __bfloat162float(hi.b[0]));
                lo.b[1] = __float2bfloat16(v0.y - __bfloat162float(hi.b[1]));
                lo.b[2] = __float2bfloat16(v0.z - __bfloat162float(hi.b[2]));
                lo.b[3] = __float2bfloat16(v0.w - __bfloat162float(hi.b[3]));
                lo.b[4] = __float2bfloat16(v1.x - __bfloat162float(hi.b[4]));
                lo.b[5] = __float2bfloat16(v1.y - __bfloat162float(hi.b[5]));
                lo.b[6] = __float2bfloat16(v1.z - __bfloat162float(hi.b[6]));
                lo.b[7] = __float2bfloat16(v1.w - __bfloat162float(hi.b[7]));
                *reinterpret_cast<uint4*>(sAh + rl * 72 + c8 * 8) = hi.u;
                *reinterpret_cast<uint4*>(sAl + rl * 72 + c8 * 8) = lo.u;
            }
        }
        __syncwarp();   // cross-lane STS -> ldmatrix visibility

        // ---- mma.sync: this warp's 32 rows x 64 cols, 3-pass bf16 hi/lo ----
        float acc[2][8][4];
#pragma unroll
        for (int mt = 0; mt < 2; mt++)
#pragma unroll
            for (int nt = 0; nt < 8; nt++)
#pragma unroll
                for (int i = 0; i < 4; i++) acc[mt][nt][i] = 0.f;

#pragma unroll
        for (int ks = 0; ks < 4; ks++) {
            uint32_t bhl[8][4];
            const uint32_t brow = aW + (ks * 16 + (lane & 15)) * 144
                                  + ((lane & 16) ? 9216u : 0u);
#pragma unroll
            for (int nt = 0; nt < 8; nt++)
                LDMB4T(bhl[nt], brow + nt * 16);

#pragma unroll
            for (int mt = 0; mt < 2; mt++) {
                const uint32_t arow = (mt * 16 + (lane & 15)) * 144
                                      + ks * 32 + ((lane >> 4) << 4);
                uint32_t ah[4], al[4];
                LDMA4(ah, aAh + arow);
                LDMA4(al, aAl + arow);
#pragma unroll
                for (int nt = 0; nt < 8; nt++) {
                    MMA16816(acc[mt][nt], ah, &bhl[nt][0]);
                    MMA16816(acc[mt][nt], ah, &bhl[nt][2]);
                    MMA16816(acc[mt][nt], al, &bhl[nt][0]);
                }
            }
        }
        __syncwarp();   // ldmatrix reads done before next tile's gather STS

        // ---- Epilogue DIRECT from acc regs ----
        const int rq = lane >> 2;
        const int cb = (lane & 3) * 2;
#pragma unroll
        for (int mt = 0; mt < 2; mt++) {
            const int rl1 = mt * 16 + rq;
            const int rl2 = rl1 + 8;
            int o1, o2;
            if (SCATTER) {
                o1 = __shfl_sync(0xffffffffu, myorow, rl1);
                o2 = __shfl_sync(0xffffffffu, myorow, rl2);
            } else {
                o1 = base + w * 32 + rl1;
                o2 = base + w * 32 + rl2;
            }
            if (o1 < N_VOX) {
                float* d = H + (size_t)o1 * 64 + cb;
                if (SCATTER) {
#pragma unroll
                    for (int nt = 0; nt < 8; nt++)
                        RED2(d + nt * 8, acc[mt][nt][0], acc[mt][nt][1]);
                } else {
#pragma unroll
                    for (int nt = 0; nt < 8; nt++)
                        *reinterpret_cast<float2*>(d + nt * 8) =
                            make_float2(acc[mt][nt][0], acc[mt][nt][1]);
                }
            }
            if (o2 < N_VOX) {
                float* d = H + (size_t)o2 * 64 + cb;
                if (SCATTER) {
#pragma unroll
                    for (int nt = 0; nt < 8; nt++)
                        RED2(d + nt * 8, acc[mt][nt][2], acc[mt][nt][3]);
                } else {
#pragma unroll
                    for (int nt = 0; nt < 8; nt++)
                        *reinterpret_cast<float2*>(d + nt * 8) =
                            make_float2(acc[mt][nt][2], acc[mt][nt][3]);
                }
            }
        }

        // advance pipeline
        myrow = nrow; myorow = norow; tfirst = nfirst;
    }
}

// ---------------------------------------------------------------------------
// W prep: bf16 hi/lo split into padded [27][2][64(k)][72(n)]
__global__ void wprep_kernel(const float* __restrict__ W)
{
    const int o = blockIdx.x;
    const int t = threadIdx.x;   // 128
    for (int idx = t; idx < 4608; idx += 128) {
        const int k = idx / 72, n = idx % 72;
        float v = (n < 64) ? W[(size_t)o * 4096 + k * 64 + n] : 0.f;
        __nv_bfloat16 hi = __float2bfloat16(v);
        __nv_bfloat16 lo = __float2bfloat16(v - __bfloat162float(hi));
        g_wb[(size_t)o * 9216 + idx]        = hi;
        g_wb[(size_t)o * 9216 + 4608 + idx] = lo;
    }
}

// ---------------------------------------------------------------------------
__global__ void zero_stats_kernel() { g_stats[threadIdx.x] = 0.f; }

// 4 independent row loads per iteration (MLP 4+) — N_VOX % 4 == 0 so only
// the r < N_VOX guard is needed.
__global__ void stats_kernel(const float* __restrict__ h, int statoff)
{
    const int t  = threadIdx.x;          // 256
    const int ch = t & 63;
    const int g  = t >> 6;               // 0..3
    float s = 0.f, sq = 0.f;
    for (int r = (blockIdx.x * 4 + g) * 4; r < N_VOX; r += gridDim.x * 16) {
        float v0 = h[(size_t)(r + 0) * 64 + ch];
        float v1 = h[(size_t)(r + 1) * 64 + ch];
        float v2 = h[(size_t)(r + 2) * 64 + ch];
        float v3 = h[(size_t)(r + 3) * 64 + ch];
        s += v0; sq = fmaf(v0, v0, sq);
        s += v1; sq = fmaf(v1, v1, sq);
        s += v2; sq = fmaf(v2, v2, sq);
        s += v3; sq = fmaf(v3, v3, sq);
    }
    __shared__ float sh[2][4][64];
    sh[0][g][ch] = s;
    sh[1][g][ch] = sq;
    __syncthreads();
    if (t < 64) {
        float ss = sh[0][0][t] + sh[0][1][t] + sh[0][2][t] + sh[0][3][t];
        atomicAdd(&g_stats[statoff + t], ss);
    } else if (t < 128) {
        int c = t - 64;
        float qq = sh[1][0][c] + sh[1][1][c] + sh[1][2][c] + sh[1][3][c];
        atomicAdd(&g_stats[statoff + 64 + c], qq);
    }
}

__global__ void finalize_stats_kernel(const float* __restrict__ gamma,
                                      const float* __restrict__ beta,
                                      int statoff, int coefoff)
{
    const int c = threadIdx.x;  // 64
    const float inv_n = 1.0f / (float)N_VOX;
    float mu  = g_stats[statoff + c] * inv_n;
    float var = g_stats[statoff + 64 + c] * inv_n - mu * mu;
    float sc  = gamma[c] * rsqrtf(var + EPSV);
    g_coef[coefoff + c]      = sc;
    g_coef[coefoff + 64 + c] = beta[c] - mu * sc;
}

// out = relu(bn2(h2) + x)
__global__ void final_kernel(const float* __restrict__ h2,
                             const float* __restrict__ x,
                             float* __restrict__ out, int coefoff)
{
    int kk = blockIdx.x * blockDim.x + threadIdx.x;
    if (kk >= N_VOX * 16) return;
    int cb = (kk & 15) * 4;
    float4 v = reinterpret_cast<const float4*>(h2)[kk];
    float4 r = reinterpret_cast<const float4*>(x)[kk];
    float s0 = g_coef[coefoff + cb + 0], b0 = g_coef[coefoff + 64 + cb + 0];
    float s1 = g_coef[coefoff + cb + 1], b1 = g_coef[coefoff + 64 + cb + 1];
    float s2 = g_coef[coefoff + cb + 2], b2 = g_coef[coefoff + 64 + cb + 2];
    float s3 = g_coef[coefoff + cb + 3], b3 = g_coef[coefoff + 64 + cb + 3];
    v.x = fmaxf(fmaf(v.x, s0, b0) + r.x, 0.f);
    v.y = fmaxf(fmaf(v.y, s1, b1) + r.y, 0.f);
    v.z = fmaxf(fmaf(v.z, s2, b2) + r.z, 0.f);
    v.w = fmaxf(fmaf(v.w, s3, b3) + r.w, 0.f);
    reinterpret_cast<float4*>(out)[kk] = v;
}

// ---------------------------------------------------------------------------
extern "C" void kernel_launch(void* const* d_in, const int* in_sizes, int n_in,
                              void* d_out, int out_size)
{
    const float* x      = (const float*)d_in[0];
    const float* W1     = (const float*)d_in[1];
    const float* gamma1 = (const float*)d_in[2];
    const float* beta1  = (const float*)d_in[3];
    const float* W2     = (const float*)d_in[4];
    const float* gamma2 = (const float*)d_in[5];
    const float* beta2  = (const float*)d_in[6];
    const int*   in_map = (const int*)d_in[7];
    const int*   out_map= (const int*)d_in[8];
    float*       out    = (float*)d_out;

    float* h1;  cudaGetSymbolAddress((void**)&h1, g_h1);
    float* h2;  cudaGetSymbolAddress((void**)&h2, g_h2);
    __nv_bfloat16* wb;  cudaGetSymbolAddress((void**)&wb, g_wb);

    cudaFuncSetAttribute(conv_mma_kernel<true, false>,
                         cudaFuncAttributeMaxDynamicSharedMemorySize, DSMEM_BYTES);
    cudaFuncSetAttribute(conv_mma_kernel<false, false>,
                         cudaFuncAttributeMaxDynamicSharedMemorySize, DSMEM_BYTES);
    cudaFuncSetAttribute(conv_mma_kernel<true, true>,
                         cudaFuncAttributeMaxDynamicSharedMemorySize, DSMEM_BYTES);
    cudaFuncSetAttribute(conv_mma_kernel<false, true>,
                         cudaFuncAttributeMaxDynamicSharedMemorySize, DSMEM_BYTES);

    const dim3 scat_grid(PP / (128 * TILES), 26);
    const int  center_blocks = (N_VOX + 128 * TILES - 1) / (128 * TILES);
    const int  ew_blocks     = (N_VOX * 16 + 255) / 256;

    zero_stats_kernel<<<1, 256>>>();

    // conv1 (raw x)
    wprep_kernel<<<27, 128>>>(W1);
    conv_mma_kernel<false, false><<<center_blocks, 128, DSMEM_BYTES>>>(x, wb, nullptr, nullptr, h1);
    conv_mma_kernel<true,  false><<<scat_grid,     128, DSMEM_BYTES>>>(x, wb, in_map, out_map, h1);
    stats_kernel<<<1024, 256>>>(h1, 0);
    finalize_stats_kernel<<<1, 64>>>(gamma1, beta1, 0, 0);

    // conv2: BN1+ReLU fused into the gather (h1 stays raw)
    wprep_kernel<<<27, 128>>>(W2);
    conv_mma_kernel<false, true><<<center_blocks, 128, DSMEM_BYTES>>>(h1, wb, nullptr, nullptr, h2);
    conv_mma_kernel<true,  true><<<scat_grid,     128, DSMEM_BYTES>>>(h1, wb, in_map, out_map, h2);
    stats_kernel<<<1024, 256>>>(h2, 128);
    finalize_stats_kernel<<<1, 64>>>(gamma2, beta2, 128, 128);

    // bn2 + residual + relu -> d_out
    final_kernel<<<ew_blocks, 256>>>(h2, x, out, 128);
}

// round 14
// speedup vs baseline: 1.2106x; 1.2106x over previous
#include <cuda_runtime.h>
#include <cuda_fp16.h>
#include <cstdint>

#define N_VOX 200000
#define PP    65536
#define EPSV  1e-5f
#define TILES 8

// ---- scratch (__device__ globals; allocation-free rule) ----
__device__ float g_h1[(size_t)N_VOX * 64];
__device__ float g_h2[(size_t)N_VOX * 64];
__device__ __half g_wh[27 * 4608];  // [27][64 k][72 n padded] fp16
__device__ float g_stats[256];
__device__ float g_coef[256];

#define RED2(p, a, b) \
    asm volatile("red.global.add.v2.f32 [%0], {%1,%2};" \
                 :: "l"(p), "f"(a), "f"(b) : "memory")

#define LDMA4(r, addr) \
    asm volatile("ldmatrix.sync.aligned.m8n8.x4.shared.b16 {%0,%1,%2,%3}, [%4];" \
                 : "=r"((r)[0]), "=r"((r)[1]), "=r"((r)[2]), "=r"((r)[3]) : "r"(addr))

// x4.trans, two nt groups per instruction: lanes 0-15 -> nt even, 16-31 -> nt odd
#define LDMB4T(r, addr) \
    asm volatile("ldmatrix.sync.aligned.m8n8.x4.trans.shared.b16 {%0,%1,%2,%3}, [%4];" \
                 : "=r"((r)[0]), "=r"((r)[1]), "=r"((r)[2]), "=r"((r)[3]) : "r"(addr))

#define MMA16816(d, a, b) \
    asm volatile("mma.sync.aligned.m16n8k16.row.col.f32.f16.f16.f32 " \
                 "{%0,%1,%2,%3},{%4,%5,%6,%7},{%8,%9},{%0,%1,%2,%3};" \
                 : "+f"((d)[0]), "+f"((d)[1]), "+f"((d)[2]), "+f"((d)[3]) \
                 : "r"((a)[0]), "r"((a)[1]), "r"((a)[2]), "r"((a)[3]), \
                   "r"((b)[0]), "r"((b)[1]))

// smem layout (bytes):
//   [0, 18432): four 4608B warp chunks: sA fp16[32][72]
//   [18432, 27648): sW fp16 [64 k][72 n], staged once per block
#define WCHUNK 4608
#define DSMEM_BYTES 27648

// ---------------------------------------------------------------------------
template <bool SCATTER, bool FUSE_BN>
__global__ __launch_bounds__(128, 4)
void conv_mma_kernel(const float* __restrict__ x,
                     const __half* __restrict__ wh,
                     const int* __restrict__ in_map,
                     const int* __restrict__ out_map,
                     float* __restrict__ H)
{
    extern __shared__ char sm[];

    const int t    = threadIdx.x;
    const int w    = t >> 5;
    const int lane = t & 31;

    __half* sA = reinterpret_cast<__half*>(sm + w * WCHUNK);

    const int ky = SCATTER ? blockIdx.y : 0;
    const int o  = SCATTER ? (ky < 13 ? ky : ky + 1) : 13;

    // Stage W_o once per block (9216 B = 1152 uint2, 9 per thread)
    {
        const uint2* src = reinterpret_cast<const uint2*>(wh + (size_t)o * 4608);
        uint2*       dst = reinterpret_cast<uint2*>(sm + 18432);
#pragma unroll
        for (int i = 0; i < 9; i++) dst[t + i * 128] = src[t + i * 128];
    }
    __syncthreads();   // only block barrier

    const uint32_t aA = (uint32_t)__cvta_generic_to_shared(sA);
    const uint32_t aW = (uint32_t)__cvta_generic_to_shared(sm + 18432);

    // gather mapping: 8 lanes per row -> 4 rows per warp instruction
    const int rsub = lane >> 3;       // 0..3
    const int c8   = lane & 7;        // 8-float column group

    float4 sc0, sc1, sb0, sb1;
    if (FUSE_BN) {
        sc0 = *reinterpret_cast<const float4*>(&g_coef[c8 * 8]);
        sc1 = *reinterpret_cast<const float4*>(&g_coef[c8 * 8 + 4]);
        sb0 = *reinterpret_cast<const float4*>(&g_coef[64 + c8 * 8]);
        sb1 = *reinterpret_cast<const float4*>(&g_coef[64 + c8 * 8 + 4]);
    }

    // pipelined map load: tile 0's maps loaded before the loop
    int myrow = 0, myorow = 0, tfirst = 0;
    if (SCATTER) {
        const size_t kb0 = (size_t)ky * PP + (size_t)blockIdx.x * TILES * 128;
        tfirst = __ldg(&in_map[kb0]);
        myrow  = __ldg(&in_map[kb0 + t]);
        myorow = __ldg(&out_map[kb0 + t]);
    }

    for (int tt = 0; tt < TILES; tt++) {
        const int base = (blockIdx.x * TILES + tt) * 128;
        if (!SCATTER && base >= N_VOX) break;
        if (SCATTER && tfirst >= N_VOX) break;   // tail-packed sentinels

        // prefetch next tile's maps
        int nrow = 0, norow = 0, nfirst = N_VOX;
        if (SCATTER && tt + 1 < TILES) {
            const size_t kbn = (size_t)ky * PP + (size_t)(base + 128);
            nfirst = __ldg(&in_map[kbn]);
            nrow   = __ldg(&in_map[kbn + t]);
            norow  = __ldg(&out_map[kbn + t]);
        }

        // ---- Gather (+ fused BN1+ReLU) -> fp16, one STS.128 per row-part ----
        {
            const float4* x4 = reinterpret_cast<const float4*>(x);
#pragma unroll
            for (int j = 0; j < 8; j++) {
                const int rl  = j * 4 + rsub;     // local row 0..31
                const int row = SCATTER ? __shfl_sync(0xffffffffu, myrow, rl)
                                        : (base + w * 32 + rl);
                float4 v0 = make_float4(0.f, 0.f, 0.f, 0.f), v1 = v0;
                if (row < N_VOX) {
                    v0 = x4[(size_t)row * 16 + c8 * 2];
                    v1 = x4[(size_t)row * 16 + c8 * 2 + 1];
                }
                if (FUSE_BN) {
                    v0.x = fmaxf(fmaf(v0.x, sc0.x, sb0.x), 0.f);
                    v0.y = fmaxf(fmaf(v0.y, sc0.y, sb0.y), 0.f);
                    v0.z = fmaxf(fmaf(v0.z, sc0.z, sb0.z), 0.f);
                    v0.w = fmaxf(fmaf(v0.w, sc0.w, sb0.w), 0.f);
                    v1.x = fmaxf(fmaf(v1.x, sc1.x, sb1.x), 0.f);
                    v1.y = fmaxf(fmaf(v1.y, sc1.y, sb1.y), 0.f);
                    v1.z = fmaxf(fmaf(v1.z, sc1.z, sb1.z), 0.f);
                    v1.w = fmaxf(fmaf(v1.w, sc1.w, sb1.w), 0.f);
                }
                union { __half2 h[4]; uint4 u; } pk;
                pk.h[0] = __float22half2_rn(make_float2(v0.x, v0.y));
                pk.h[1] = __float22half2_rn(make_float2(v0.z, v0.w));
                pk.h[2] = __float22half2_rn(make_float2(v1.x, v1.y));
                pk.h[3] = __float22half2_rn(make_float2(v1.z, v1.w));
                *reinterpret_cast<uint4*>(sA + rl * 72 + c8 * 8) = pk.u;
            }
        }
        __syncwarp();   // cross-lane STS -> ldmatrix visibility

        // ---- mma.sync: this warp's 32 rows x 64 cols, SINGLE-PASS fp16 ----
        float acc[2][8][4];
#pragma unroll
        for (int mt = 0; mt < 2; mt++)
#pragma unroll
            for (int nt = 0; nt < 8; nt++)
#pragma unroll
                for (int i = 0; i < 4; i++) acc[mt][nt][i] = 0.f;

#pragma unroll
        for (int ks = 0; ks < 4; ks++) {
            // B: 4 x4.trans per ks, each feeding two nt groups
            uint32_t bb[4][4];
            const uint32_t brow = aW + (ks * 16 + (lane & 15)) * 144
                                  + ((lane & 16) ? 16u : 0u);
#pragma unroll
            for (int p = 0; p < 4; p++)
                LDMB4T(bb[p], brow + p * 32);

#pragma unroll
            for (int mt = 0; mt < 2; mt++) {
                const uint32_t arow = (mt * 16 + (lane & 15)) * 144
                                      + ks * 32 + ((lane >> 4) << 4);
                uint32_t a[4];
                LDMA4(a, aA + arow);
#pragma unroll
                for (int p = 0; p < 4; p++) {
                    MMA16816(acc[mt][2 * p],     a, &bb[p][0]);
                    MMA16816(acc[mt][2 * p + 1], a, &bb[p][2]);
                }
            }
        }
        __syncwarp();   // ldmatrix reads done before next tile's gather STS

        // ---- Epilogue DIRECT from acc regs ----
        const int rq = lane >> 2;
        const int cb = (lane & 3) * 2;
#pragma unroll
        for (int mt = 0; mt < 2; mt++) {
            const int rl1 = mt * 16 + rq;
            const int rl2 = rl1 + 8;
            int o1, o2;
            if (SCATTER) {
                o1 = __shfl_sync(0xffffffffu, myorow, rl1);
                o2 = __shfl_sync(0xffffffffu, myorow, rl2);
            } else {
                o1 = base + w * 32 + rl1;
                o2 = base + w * 32 + rl2;
            }
            if (o1 < N_VOX) {
                float* d = H + (size_t)o1 * 64 + cb;
                if (SCATTER) {
#pragma unroll
                    for (int nt = 0; nt < 8; nt++)
                        RED2(d + nt * 8, acc[mt][nt][0], acc[mt][nt][1]);
                } else {
#pragma unroll
                    for (int nt = 0; nt < 8; nt++)
                        *reinterpret_cast<float2*>(d + nt * 8) =
                            make_float2(acc[mt][nt][0], acc[mt][nt][1]);
                }
            }
            if (o2 < N_VOX) {
                float* d = H + (size_t)o2 * 64 + cb;
                if (SCATTER) {
#pragma unroll
                    for (int nt = 0; nt < 8; nt++)
                        RED2(d + nt * 8, acc[mt][nt][2], acc[mt][nt][3]);
                } else {
#pragma unroll
                    for (int nt = 0; nt < 8; nt++)
                        *reinterpret_cast<float2*>(d + nt * 8) =
                            make_float2(acc[mt][nt][2], acc[mt][nt][3]);
                }
            }
        }

        // advance pipeline
        myrow = nrow; myorow = norow; tfirst = nfirst;
    }
}

// ---------------------------------------------------------------------------
// W prep: fp16 into padded [27][64(k)][72(n)]
__global__ void wprep_kernel(const float* __restrict__ W)
{
    const int o = blockIdx.x;
    const int t = threadIdx.x;   // 128
    for (int idx = t; idx < 4608; idx += 128) {
        const int k = idx / 72, n = idx % 72;
        float v = (n < 64) ? W[(size_t)o * 4096 + k * 64 + n] : 0.f;
        g_wh[(size_t)o * 4608 + idx] = __float2half(v);
    }
}

// ---------------------------------------------------------------------------
__global__ void zero_stats_kernel() { g_stats[threadIdx.x] = 0.f; }

__global__ void stats_kernel(const float* __restrict__ h, int statoff)
{
    const int t = threadIdx.x;          // 256
    const int ch = t & 63;
    const int g  = t >> 6;
    float s = 0.f, sq = 0.f;
#pragma unroll 4
    for (int row = blockIdx.x * 4 + g; row < N_VOX; row += gridDim.x * 4) {
        float v = h[(size_t)row * 64 + ch];
        s += v; sq = fmaf(v, v, sq);
    }
    __shared__ float sh[2][4][64];
    sh[0][g][ch] = s;
    sh[1][g][ch] = sq;
    __syncthreads();
    if (t < 64) {
        float ss = sh[0][0][t] + sh[0][1][t] + sh[0][2][t] + sh[0][3][t];
        atomicAdd(&g_stats[statoff + t], ss);
    } else if (t < 128) {
        int c = t - 64;
        float qq = sh[1][0][c] + sh[1][1][c] + sh[1][2][c] + sh[1][3][c];
        atomicAdd(&g_stats[statoff + 64 + c], qq);
    }
}

__global__ void finalize_stats_kernel(const float* __restrict__ gamma,
                                      const float* __restrict__ beta,
                                      int statoff, int coefoff)
{
    const int c = threadIdx.x;  // 64
    const float inv_n = 1.0f / (float)N_VOX;
    float mu  = g_stats[statoff + c] * inv_n;
    float var = g_stats[statoff + 64 + c] * inv_n - mu * mu;
    float sc  = gamma[c] * rsqrtf(var + EPSV);
    g_coef[coefoff + c]      = sc;
    g_coef[coefoff + 64 + c] = beta[c] - mu * sc;
}

// out = relu(bn2(h2) + x)
__global__ void final_kernel(const float* __restrict__ h2,
                             const float* __restrict__ x,
                             float* __restrict__ out, int coefoff)
{
    int kk = blockIdx.x * blockDim.x + threadIdx.x;
    if (kk >= N_VOX * 16) return;
    int cb = (kk & 15) * 4;
    float4 v = reinterpret_cast<const float4*>(h2)[kk];
    float4 r = reinterpret_cast<const float4*>(x)[kk];
    float s0 = g_coef[coefoff + cb + 0], b0 = g_coef[coefoff + 64 + cb + 0];
    float s1 = g_coef[coefoff + cb + 1], b1 = g_coef[coefoff + 64 + cb + 1];
    float s2 = g_coef[coefoff + cb + 2], b2 = g_coef[coefoff + 64 + cb + 2];
    float s3 = g_coef[coefoff + cb + 3], b3 = g_coef[coefoff + 64 + cb + 3];
    v.x = fmaxf(fmaf(v.x, s0, b0) + r.x, 0.f);
    v.y = fmaxf(fmaf(v.y, s1, b1) + r.y, 0.f);
    v.z = fmaxf(fmaf(v.z, s2, b2) + r.z, 0.f);
    v.w = fmaxf(fmaf(v.w, s3, b3) + r.w, 0.f);
    reinterpret_cast<float4*>(out)[kk] = v;
}

// ---------------------------------------------------------------------------
extern "C" void kernel_launch(void* const* d_in, const int* in_sizes, int n_in,
                              void* d_out, int out_size)
{
    const float* x      = (const float*)d_in[0];
    const float* W1     = (const float*)d_in[1];
    const float* gamma1 = (const float*)d_in[2];
    const float* beta1  = (const float*)d_in[3];
    const float* W2     = (const float*)d_in[4];
    const float* gamma2 = (const float*)d_in[5];
    const float* beta2  = (const float*)d_in[6];
    const int*   in_map = (const int*)d_in[7];
    const int*   out_map= (const int*)d_in[8];
    float*       out    = (float*)d_out;

    float* h1;  cudaGetSymbolAddress((void**)&h1, g_h1);
    float* h2;  cudaGetSymbolAddress((void**)&h2, g_h2);
    __half* wh; cudaGetSymbolAddress((void**)&wh, g_wh);

    const dim3 scat_grid(PP / (128 * TILES), 26);
    const int  center_blocks = (N_VOX + 128 * TILES - 1) / (128 * TILES);
    const int  ew_blocks     = (N_VOX * 16 + 255) / 256;

    zero_stats_kernel<<<1, 256>>>();

    // conv1 (raw x)
    wprep_kernel<<<27, 128>>>(W1);
    conv_mma_kernel<false, false><<<center_blocks, 128, DSMEM_BYTES>>>(x, wh, nullptr, nullptr, h1);
    conv_mma_kernel<true,  false><<<scat_grid,     128, DSMEM_BYTES>>>(x, wh, in_map, out_map, h1);
    stats_kernel<<<1024, 256>>>(h1, 0);
    finalize_stats_kernel<<<1, 64>>>(gamma1, beta1, 0, 0);

    // conv2: BN1+ReLU fused into the gather (h1 stays raw)
    wprep_kernel<<<27, 128>>>(W2);
    conv_mma_kernel<false, true><<<center_blocks, 128, DSMEM_BYTES>>>(h1, wh, nullptr, nullptr, h2);
    conv_mma_kernel<true,  true><<<scat_grid,     128, DSMEM_BYTES>>>(h1, wh, in_map, out_map, h2);
    stats_kernel<<<1024, 256>>>(h2, 128);
    finalize_stats_kernel<<<1, 64>>>(gamma2, beta2, 128, 128);

    // bn2 + residual + relu -> d_out
    final_kernel<<<ew_blocks, 256>>>(h2, x, out, 128);
}

// round 15
// speedup vs baseline: 1.2805x; 1.0577x over previous
#include <cuda_runtime.h>
#include <cuda_fp16.h>
#include <cstdint>

#define N_VOX 200000
#define PP    65536
#define EPSV  1e-5f
#define TILES 8

// ---- scratch (__device__ globals; allocation-free rule) ----
__device__ float g_h1[(size_t)N_VOX * 64];
__device__ float g_h2[(size_t)N_VOX * 64];
__device__ __half g_wh[27 * 4608];  // [27][64 k][72 n padded] fp16, COLUMN-INTERLEAVED
__device__ float g_stats[256];
__device__ float g_coef[256];

#define RED4(p, a, b, c, d) \
    asm volatile("red.global.add.v4.f32 [%0], {%1,%2,%3,%4};" \
                 :: "l"(p), "f"(a), "f"(b), "f"(c), "f"(d) : "memory")

#define LDMA4(r, addr) \
    asm volatile("ldmatrix.sync.aligned.m8n8.x4.shared.b16 {%0,%1,%2,%3}, [%4];" \
                 : "=r"((r)[0]), "=r"((r)[1]), "=r"((r)[2]), "=r"((r)[3]) : "r"(addr))

// x4.trans, two nt groups per instruction: lanes 0-15 -> nt even, 16-31 -> nt odd
#define LDMB4T(r, addr) \
    asm volatile("ldmatrix.sync.aligned.m8n8.x4.trans.shared.b16 {%0,%1,%2,%3}, [%4];" \
                 : "=r"((r)[0]), "=r"((r)[1]), "=r"((r)[2]), "=r"((r)[3]) : "r"(addr))

#define MMA16816(d, a, b) \
    asm volatile("mma.sync.aligned.m16n8k16.row.col.f32.f16.f16.f32 " \
                 "{%0,%1,%2,%3},{%4,%5,%6,%7},{%8,%9},{%0,%1,%2,%3};" \
                 : "+f"((d)[0]), "+f"((d)[1]), "+f"((d)[2]), "+f"((d)[3]) \
                 : "r"((a)[0]), "r"((a)[1]), "r"((a)[2]), "r"((a)[3]), \
                   "r"((b)[0]), "r"((b)[1]))

// smem layout (bytes):
//   [0, 18432): four 4608B warp chunks: sA fp16[32][72]
//   [18432, 27648): sW fp16 [64 k][72 n permuted], staged once per block
#define WCHUNK 4608
#define DSMEM_BYTES 27648

// ---------------------------------------------------------------------------
template <bool SCATTER, bool FUSE_BN>
__global__ __launch_bounds__(128, 4)
void conv_mma_kernel(const float* __restrict__ x,
                     const __half* __restrict__ wh,
                     const int* __restrict__ in_map,
                     const int* __restrict__ out_map,
                     float* __restrict__ H)
{
    extern __shared__ char sm[];

    const int t    = threadIdx.x;
    const int w    = t >> 5;
    const int lane = t & 31;

    __half* sA = reinterpret_cast<__half*>(sm + w * WCHUNK);

    const int ky = SCATTER ? blockIdx.y : 0;
    const int o  = SCATTER ? (ky < 13 ? ky : ky + 1) : 13;

    // Stage W_o once per block (9216 B)
    {
        const uint2* src = reinterpret_cast<const uint2*>(wh + (size_t)o * 4608);
        uint2*       dst = reinterpret_cast<uint2*>(sm + 18432);
#pragma unroll
        for (int i = 0; i < 9; i++) dst[t + i * 128] = src[t + i * 128];
    }
    __syncthreads();   // only block barrier

    const uint32_t aA = (uint32_t)__cvta_generic_to_shared(sA);
    const uint32_t aW = (uint32_t)__cvta_generic_to_shared(sm + 18432);

    // gather mapping: 8 lanes per row -> 4 rows per warp instruction
    const int rsub = lane >> 3;       // 0..3
    const int c8   = lane & 7;        // 8-float column group

    float4 sc0, sc1, sb0, sb1;
    if (FUSE_BN) {
        sc0 = *reinterpret_cast<const float4*>(&g_coef[c8 * 8]);
        sc1 = *reinterpret_cast<const float4*>(&g_coef[c8 * 8 + 4]);
        sb0 = *reinterpret_cast<const float4*>(&g_coef[64 + c8 * 8]);
        sb1 = *reinterpret_cast<const float4*>(&g_coef[64 + c8 * 8 + 4]);
    }

    // pipelined map load: tile 0's maps loaded before the loop
    int myrow = 0, myorow = 0, tfirst = 0;
    if (SCATTER) {
        const size_t kb0 = (size_t)ky * PP + (size_t)blockIdx.x * TILES * 128;
        tfirst = __ldg(&in_map[kb0]);
        myrow  = __ldg(&in_map[kb0 + t]);
        myorow = __ldg(&out_map[kb0 + t]);
    }

    for (int tt = 0; tt < TILES; tt++) {
        const int base = (blockIdx.x * TILES + tt) * 128;
        if (!SCATTER && base >= N_VOX) break;
        if (SCATTER && tfirst >= N_VOX) break;   // tail-packed sentinels

        // prefetch next tile's maps
        int nrow = 0, norow = 0, nfirst = N_VOX;
        if (SCATTER && tt + 1 < TILES) {
            const size_t kbn = (size_t)ky * PP + (size_t)(base + 128);
            nfirst = __ldg(&in_map[kbn]);
            nrow   = __ldg(&in_map[kbn + t]);
            norow  = __ldg(&out_map[kbn + t]);
        }

        // ---- Gather (+ fused BN1+ReLU) -> fp16, one STS.128 per row-part ----
        {
            const float4* x4 = reinterpret_cast<const float4*>(x);
#pragma unroll
            for (int j = 0; j < 8; j++) {
                const int rl  = j * 4 + rsub;     // local row 0..31
                const int row = SCATTER ? __shfl_sync(0xffffffffu, myrow, rl)
                                        : (base + w * 32 + rl);
                float4 v0 = make_float4(0.f, 0.f, 0.f, 0.f), v1 = v0;
                if (row < N_VOX) {
                    v0 = x4[(size_t)row * 16 + c8 * 2];
                    v1 = x4[(size_t)row * 16 + c8 * 2 + 1];
                }
                if (FUSE_BN) {
                    v0.x = fmaxf(fmaf(v0.x, sc0.x, sb0.x), 0.f);
                    v0.y = fmaxf(fmaf(v0.y, sc0.y, sb0.y), 0.f);
                    v0.z = fmaxf(fmaf(v0.z, sc0.z, sb0.z), 0.f);
                    v0.w = fmaxf(fmaf(v0.w, sc0.w, sb0.w), 0.f);
                    v1.x = fmaxf(fmaf(v1.x, sc1.x, sb1.x), 0.f);
                    v1.y = fmaxf(fmaf(v1.y, sc1.y, sb1.y), 0.f);
                    v1.z = fmaxf(fmaf(v1.z, sc1.z, sb1.z), 0.f);
                    v1.w = fmaxf(fmaf(v1.w, sc1.w, sb1.w), 0.f);
                }
                union { __half2 h[4]; uint4 u; } pk;
                pk.h[0] = __float22half2_rn(make_float2(v0.x, v0.y));
                pk.h[1] = __float22half2_rn(make_float2(v0.z, v0.w));
                pk.h[2] = __float22half2_rn(make_float2(v1.x, v1.y));
                pk.h[3] = __float22half2_rn(make_float2(v1.z, v1.w));
                *reinterpret_cast<uint4*>(sA + rl * 72 + c8 * 8) = pk.u;
            }
        }
        __syncwarp();   // cross-lane STS -> ldmatrix visibility

        // ---- mma.sync: this warp's 32 rows x 64 cols, single-pass fp16 ----
        float acc[2][8][4];
#pragma unroll
        for (int mt = 0; mt < 2; mt++)
#pragma unroll
            for (int nt = 0; nt < 8; nt++)
#pragma unroll
                for (int i = 0; i < 4; i++) acc[mt][nt][i] = 0.f;

#pragma unroll
        for (int ks = 0; ks < 4; ks++) {
            uint32_t bb[4][4];
            const uint32_t brow = aW + (ks * 16 + (lane & 15)) * 144
                                  + ((lane & 16) ? 16u : 0u);
#pragma unroll
            for (int p = 0; p < 4; p++)
                LDMB4T(bb[p], brow + p * 32);

#pragma unroll
            for (int mt = 0; mt < 2; mt++) {
                const uint32_t arow = (mt * 16 + (lane & 15)) * 144
                                      + ks * 32 + ((lane >> 4) << 4);
                uint32_t a[4];
                LDMA4(a, aA + arow);
#pragma unroll
                for (int p = 0; p < 4; p++) {
                    MMA16816(acc[mt][2 * p],     a, &bb[p][0]);
                    MMA16816(acc[mt][2 * p + 1], a, &bb[p][2]);
                }
            }
        }
        __syncwarp();   // ldmatrix reads done before next tile's gather STS

        // ---- Epilogue: W columns are interleaved so acc pair {2p,2p+1}
        //      gives lane q 4 CONTIGUOUS original cols 16p+4q.. -> RED4/STG4 ----
        const int rq = lane >> 2;
        const int cq = (lane & 3) * 4;
#pragma unroll
        for (int mt = 0; mt < 2; mt++) {
            const int rl1 = mt * 16 + rq;
            const int rl2 = rl1 + 8;
            int o1, o2;
            if (SCATTER) {
                o1 = __shfl_sync(0xffffffffu, myorow, rl1);
                o2 = __shfl_sync(0xffffffffu, myorow, rl2);
            } else {
                o1 = base + w * 32 + rl1;
                o2 = base + w * 32 + rl2;
            }
            if (o1 < N_VOX) {
                float* d = H + (size_t)o1 * 64 + cq;
#pragma unroll
                for (int p = 0; p < 4; p++) {
                    if (SCATTER)
                        RED4(d + p * 16, acc[mt][2 * p][0], acc[mt][2 * p][1],
                                         acc[mt][2 * p + 1][0], acc[mt][2 * p + 1][1]);
                    else
                        *reinterpret_cast<float4*>(d + p * 16) =
                            make_float4(acc[mt][2 * p][0], acc[mt][2 * p][1],
                                        acc[mt][2 * p + 1][0], acc[mt][2 * p + 1][1]);
                }
            }
            if (o2 < N_VOX) {
                float* d = H + (size_t)o2 * 64 + cq;
#pragma unroll
                for (int p = 0; p < 4; p++) {
                    if (SCATTER)
                        RED4(d + p * 16, acc[mt][2 * p][2], acc[mt][2 * p][3],
                                         acc[mt][2 * p + 1][2], acc[mt][2 * p + 1][3]);
                    else
                        *reinterpret_cast<float4*>(d + p * 16) =
                            make_float4(acc[mt][2 * p][2], acc[mt][2 * p][3],
                                        acc[mt][2 * p + 1][2], acc[mt][2 * p + 1][3]);
                }
            }
        }

        // advance pipeline
        myrow = nrow; myorow = norow; tfirst = nfirst;
    }
}

// ---------------------------------------------------------------------------
// W prep: fp16 into padded [27][64(k)][72(n)] with COLUMN INTERLEAVE:
// within each 16-col block (p = n/16): orig col c = 4*pair+sub (pair 0..3,
// sub 0..3) -> slot p*16 + (sub<2 ? 2*pair+sub : 8 + 2*pair + (sub-2)).
// mma group 2p then yields even col-pairs, group 2p+1 odd pairs -> lane q
// owns contiguous orig cols 16p+4q..4q+3.
__global__ void wprep_kernel(const float* __restrict__ W)
{
    const int o = blockIdx.x;
    const int t = threadIdx.x;   // 128
    for (int idx = t; idx < 4608; idx += 128) {
        const int k = idx / 72, n = idx % 72;
        if (n >= 64) { g_wh[(size_t)o * 4608 + idx] = __float2half(0.f); continue; }
        const int p = n >> 4, c = n & 15;
        const int pair = c >> 2, sub = c & 3;
        const int slot = p * 16 + ((sub < 2) ? (pair * 2 + sub)
                                             : (8 + pair * 2 + (sub - 2)));
        float v = W[(size_t)o * 4096 + k * 64 + n];
        g_wh[(size_t)o * 4608 + k * 72 + slot] = __float2half(v);
    }
}

// ---------------------------------------------------------------------------
__global__ void zero_stats_kernel() { g_stats[threadIdx.x] = 0.f; }

__global__ void stats_kernel(const float* __restrict__ h, int statoff)
{
    const int t = threadIdx.x;          // 256
    const int ch = t & 63;
    const int g  = t >> 6;
    float s = 0.f, sq = 0.f;
#pragma unroll 4
    for (int row = blockIdx.x * 4 + g; row < N_VOX; row += gridDim.x * 4) {
        float v = h[(size_t)row * 64 + ch];
        s += v; sq = fmaf(v, v, sq);
    }
    __shared__ float sh[2][4][64];
    sh[0][g][ch] = s;
    sh[1][g][ch] = sq;
    __syncthreads();
    if (t < 64) {
        float ss = sh[0][0][t] + sh[0][1][t] + sh[0][2][t] + sh[0][3][t];
        atomicAdd(&g_stats[statoff + t], ss);
    } else if (t < 128) {
        int c = t - 64;
        float qq = sh[1][0][c] + sh[1][1][c] + sh[1][2][c] + sh[1][3][c];
        atomicAdd(&g_stats[statoff + 64 + c], qq);
    }
}

__global__ void finalize_stats_kernel(const float* __restrict__ gamma,
                                      const float* __restrict__ beta,
                                      int statoff, int coefoff)
{
    const int c = threadIdx.x;  // 64
    const float inv_n = 1.0f / (float)N_VOX;
    float mu  = g_stats[statoff + c] * inv_n;
    float var = g_stats[statoff + 64 + c] * inv_n - mu * mu;
    float sc  = gamma[c] * rsqrtf(var + EPSV);
    g_coef[coefoff + c]      = sc;
    g_coef[coefoff + 64 + c] = beta[c] - mu * sc;
}

// out = relu(bn2(h2) + x)
__global__ void final_kernel(const float* __restrict__ h2,
                             const float* __restrict__ x,
                             float* __restrict__ out, int coefoff)
{
    int kk = blockIdx.x * blockDim.x + threadIdx.x;
    if (kk >= N_VOX * 16) return;
    int cb = (kk & 15) * 4;
    float4 v = reinterpret_cast<const float4*>(h2)[kk];
    float4 r = reinterpret_cast<const float4*>(x)[kk];
    float s0 = g_coef[coefoff + cb + 0], b0 = g_coef[coefoff + 64 + cb + 0];
    float s1 = g_coef[coefoff + cb + 1], b1 = g_coef[coefoff + 64 + cb + 1];
    float s2 = g_coef[coefoff + cb + 2], b2 = g_coef[coefoff + 64 + cb + 2];
    float s3 = g_coef[coefoff + cb + 3], b3 = g_coef[coefoff + 64 + cb + 3];
    v.x = fmaxf(fmaf(v.x, s0, b0) + r.x, 0.f);
    v.y = fmaxf(fmaf(v.y, s1, b1) + r.y, 0.f);
    v.z = fmaxf(fmaf(v.z, s2, b2) + r.z, 0.f);
    v.w = fmaxf(fmaf(v.w, s3, b3) + r.w, 0.f);
    reinterpret_cast<float4*>(out)[kk] = v;
}

// ---------------------------------------------------------------------------
extern "C" void kernel_launch(void* const* d_in, const int* in_sizes, int n_in,
                              void* d_out, int out_size)
{
    const float* x      = (const float*)d_in[0];
    const float* W1     = (const float*)d_in[1];
    const float* gamma1 = (const float*)d_in[2];
    const float* beta1  = (const float*)d_in[3];
    const float* W2     = (const float*)d_in[4];
    const float* gamma2 = (const float*)d_in[5];
    const float* beta2  = (const float*)d_in[6];
    const int*   in_map = (const int*)d_in[7];
    const int*   out_map= (const int*)d_in[8];
    float*       out    = (float*)d_out;

    float* h1;  cudaGetSymbolAddress((void**)&h1, g_h1);
    float* h2;  cudaGetSymbolAddress((void**)&h2, g_h2);
    __half* wh; cudaGetSymbolAddress((void**)&wh, g_wh);

    const dim3 scat_grid(PP / (128 * TILES), 26);
    const int  center_blocks = (N_VOX + 128 * TILES - 1) / (128 * TILES);
    const int  ew_blocks     = (N_VOX * 16 + 255) / 256;

    zero_stats_kernel<<<1, 256>>>();

    // conv1 (raw x)
    wprep_kernel<<<27, 128>>>(W1);
    conv_mma_kernel<false, false><<<center_blocks, 128, DSMEM_BYTES>>>(x, wh, nullptr, nullptr, h1);
    conv_mma_kernel<true,  false><<<scat_grid,     128, DSMEM_BYTES>>>(x, wh, in_map, out_map, h1);
    stats_kernel<<<1024, 256>>>(h1, 0);
    finalize_stats_kernel<<<1, 64>>>(gamma1, beta1, 0, 0);

    // conv2: BN1+ReLU fused into the gather (h1 stays raw)
    wprep_kernel<<<27, 128>>>(W2);
    conv_mma_kernel<false, true><<<center_blocks, 128, DSMEM_BYTES>>>(h1, wh, nullptr, nullptr, h2);
    conv_mma_kernel<true,  true><<<scat_grid,     128, DSMEM_BYTES>>>(h1, wh, in_map, out_map, h2);
    stats_kernel<<<1024, 256>>>(h2, 128);
    finalize_stats_kernel<<<1, 64>>>(gamma2, beta2, 128, 128);

    // bn2 + residual + relu -> d_out
    final_kernel<<<ew_blocks, 256>>>(h2, x, out, 128);
}

// round 16
// speedup vs baseline: 1.4666x; 1.1453x over previous
#include <cuda_runtime.h>
#include <cuda_fp16.h>
#include <cstdint>

#define N_VOX 200000
#define PP    65536
#define EPSV  1e-5f
#define TILES 8

// ---- scratch (__device__ globals; allocation-free rule) ----
__device__ float g_h1[(size_t)N_VOX * 64];
__device__ float g_h2[(size_t)N_VOX * 64];
__device__ __half g_wh[27 * 4608];  // [27][64 k PERMUTED][72 n INTERLEAVED] fp16
__device__ float g_stats[256];
__device__ float g_coef[256];

#define RED4(p, a, b, c, d) \
    asm volatile("red.global.add.v4.f32 [%0], {%1,%2,%3,%4};" \
                 :: "l"(p), "f"(a), "f"(b), "f"(c), "f"(d) : "memory")

#define LDMA4(r, addr) \
    asm volatile("ldmatrix.sync.aligned.m8n8.x4.shared.b16 {%0,%1,%2,%3}, [%4];" \
                 : "=r"((r)[0]), "=r"((r)[1]), "=r"((r)[2]), "=r"((r)[3]) : "r"(addr))

#define LDMB4T(r, addr) \
    asm volatile("ldmatrix.sync.aligned.m8n8.x4.trans.shared.b16 {%0,%1,%2,%3}, [%4];" \
                 : "=r"((r)[0]), "=r"((r)[1]), "=r"((r)[2]), "=r"((r)[3]) : "r"(addr))

#define MMA16816(d, a, b) \
    asm volatile("mma.sync.aligned.m16n8k16.row.col.f32.f16.f16.f32 " \
                 "{%0,%1,%2,%3},{%4,%5,%6,%7},{%8,%9},{%0,%1,%2,%3};" \
                 : "+f"((d)[0]), "+f"((d)[1]), "+f"((d)[2]), "+f"((d)[3]) \
                 : "r"((a)[0]), "r"((a)[1]), "r"((a)[2]), "r"((a)[3]), \
                   "r"((b)[0]), "r"((b)[1]))

// smem layout (bytes):
//   [0, 18432): four 4608B warp chunks: sA fp16[32][72]
//   [18432, 27648): sW fp16 [64 k'][72 n'], staged once per block
#define WCHUNK 4608
#define DSMEM_BYTES 27648

// ---------------------------------------------------------------------------
template <bool SCATTER, bool FUSE_BN>
__global__ __launch_bounds__(128, 4)
void conv_mma_kernel(const float* __restrict__ x,
                     const __half* __restrict__ wh,
                     const int* __restrict__ in_map,
                     const int* __restrict__ out_map,
                     float* __restrict__ H)
{
    extern __shared__ char sm[];

    const int t    = threadIdx.x;
    const int w    = t >> 5;
    const int lane = t & 31;

    __half* sA = reinterpret_cast<__half*>(sm + w * WCHUNK);

    const int ky = SCATTER ? blockIdx.y : 0;
    const int o  = SCATTER ? (ky < 13 ? ky : ky + 1) : 13;

    // Stage W_o once per block (9216 B)
    {
        const uint2* src = reinterpret_cast<const uint2*>(wh + (size_t)o * 4608);
        uint2*       dst = reinterpret_cast<uint2*>(sm + 18432);
#pragma unroll
        for (int i = 0; i < 9; i++) dst[t + i * 128] = src[t + i * 128];
    }
    __syncthreads();   // only block barrier

    const uint32_t aA = (uint32_t)__cvta_generic_to_shared(sA);
    const uint32_t aW = (uint32_t)__cvta_generic_to_shared(sm + 18432);

    // gather mapping: 8 lanes per row -> 4 rows per warp instruction.
    // Lane c8 reads float4 c8 (line 0) and float4 8+c8 (line 1): both LDG.128
    // instructions touch CONTIGUOUS 128B lines (4 wf instead of 8).
    // Resulting A k-order in smem is permuted; W k-rows carry the same
    // permutation (see wprep), so the GEMM is unchanged.
    const int rsub = lane >> 3;       // 0..3
    const int c8   = lane & 7;

    float4 sc0, sc1, sb0, sb1;
    if (FUSE_BN) {
        // orig channels: v0 -> 4*c8.., v1 -> 32+4*c8..
        sc0 = *reinterpret_cast<const float4*>(&g_coef[c8 * 4]);
        sc1 = *reinterpret_cast<const float4*>(&g_coef[32 + c8 * 4]);
        sb0 = *reinterpret_cast<const float4*>(&g_coef[64 + c8 * 4]);
        sb1 = *reinterpret_cast<const float4*>(&g_coef[96 + c8 * 4]);
    }

    // pipelined map load: tile 0's maps loaded before the loop
    int myrow = 0, myorow = 0, tfirst = 0;
    if (SCATTER) {
        const size_t kb0 = (size_t)ky * PP + (size_t)blockIdx.x * TILES * 128;
        tfirst = __ldg(&in_map[kb0]);
        myrow  = __ldg(&in_map[kb0 + t]);
        myorow = __ldg(&out_map[kb0 + t]);
    }

    for (int tt = 0; tt < TILES; tt++) {
        const int base = (blockIdx.x * TILES + tt) * 128;
        if (!SCATTER && base >= N_VOX) break;
        if (SCATTER && tfirst >= N_VOX) break;   // tail-packed sentinels

        // prefetch next tile's maps
        int nrow = 0, norow = 0, nfirst = N_VOX;
        if (SCATTER && tt + 1 < TILES) {
            const size_t kbn = (size_t)ky * PP + (size_t)(base + 128);
            nfirst = __ldg(&in_map[kbn]);
            nrow   = __ldg(&in_map[kbn + t]);
            norow  = __ldg(&out_map[kbn + t]);
        }

        // ---- Gather (+ fused BN1+ReLU) -> fp16, one STS.128 per row-part ----
        {
            const float4* x4 = reinterpret_cast<const float4*>(x);
#pragma unroll
            for (int j = 0; j < 8; j++) {
                const int rl  = j * 4 + rsub;     // local row 0..31
                const int row = SCATTER ? __shfl_sync(0xffffffffu, myrow, rl)
                                        : (base + w * 32 + rl);
                float4 v0 = make_float4(0.f, 0.f, 0.f, 0.f), v1 = v0;
                if (row < N_VOX) {
                    v0 = x4[(size_t)row * 16 + c8];        // line 0
                    v1 = x4[(size_t)row * 16 + 8 + c8];    // line 1
                }
                if (FUSE_BN) {
                    v0.x = fmaxf(fmaf(v0.x, sc0.x, sb0.x), 0.f);
                    v0.y = fmaxf(fmaf(v0.y, sc0.y, sb0.y), 0.f);
                    v0.z = fmaxf(fmaf(v0.z, sc0.z, sb0.z), 0.f);
                    v0.w = fmaxf(fmaf(v0.w, sc0.w, sb0.w), 0.f);
                    v1.x = fmaxf(fmaf(v1.x, sc1.x, sb1.x), 0.f);
                    v1.y = fmaxf(fmaf(v1.y, sc1.y, sb1.y), 0.f);
                    v1.z = fmaxf(fmaf(v1.z, sc1.z, sb1.z), 0.f);
                    v1.w = fmaxf(fmaf(v1.w, sc1.w, sb1.w), 0.f);
                }
                union { __half2 h[4]; uint4 u; } pk;
                pk.h[0] = __float22half2_rn(make_float2(v0.x, v0.y));
                pk.h[1] = __float22half2_rn(make_float2(v0.z, v0.w));
                pk.h[2] = __float22half2_rn(make_float2(v1.x, v1.y));
                pk.h[3] = __float22half2_rn(make_float2(v1.z, v1.w));
                *reinterpret_cast<uint4*>(sA + rl * 72 + c8 * 8) = pk.u;
            }
        }
        __syncwarp();   // cross-lane STS -> ldmatrix visibility

        // ---- mma.sync: this warp's 32 rows x 64 cols, single-pass fp16 ----
        float acc[2][8][4];
#pragma unroll
        for (int mt = 0; mt < 2; mt++)
#pragma unroll
            for (int nt = 0; nt < 8; nt++)
#pragma unroll
                for (int i = 0; i < 4; i++) acc[mt][nt][i] = 0.f;

#pragma unroll
        for (int ks = 0; ks < 4; ks++) {
            uint32_t bb[4][4];
            const uint32_t brow = aW + (ks * 16 + (lane & 15)) * 144
                                  + ((lane & 16) ? 16u : 0u);
#pragma unroll
            for (int p = 0; p < 4; p++)
                LDMB4T(bb[p], brow + p * 32);

#pragma unroll
            for (int mt = 0; mt < 2; mt++) {
                const uint32_t arow = (mt * 16 + (lane & 15)) * 144
                                      + ks * 32 + ((lane >> 4) << 4);
                uint32_t a[4];
                LDMA4(a, aA + arow);
#pragma unroll
                for (int p = 0; p < 4; p++) {
                    MMA16816(acc[mt][2 * p],     a, &bb[p][0]);
                    MMA16816(acc[mt][2 * p + 1], a, &bb[p][2]);
                }
            }
        }
        __syncwarp();   // ldmatrix reads done before next tile's gather STS

        // ---- Epilogue: n-interleave gives lane q 4 contiguous cols -> RED4 ----
        const int rq = lane >> 2;
        const int cq = (lane & 3) * 4;
#pragma unroll
        for (int mt = 0; mt < 2; mt++) {
            const int rl1 = mt * 16 + rq;
            const int rl2 = rl1 + 8;
            int o1, o2;
            if (SCATTER) {
                o1 = __shfl_sync(0xffffffffu, myorow, rl1);
                o2 = __shfl_sync(0xffffffffu, myorow, rl2);
            } else {
                o1 = base + w * 32 + rl1;
                o2 = base + w * 32 + rl2;
            }
            if (o1 < N_VOX) {
                float* d = H + (size_t)o1 * 64 + cq;
#pragma unroll
                for (int p = 0; p < 4; p++) {
                    if (SCATTER)
                        RED4(d + p * 16, acc[mt][2 * p][0], acc[mt][2 * p][1],
                                         acc[mt][2 * p + 1][0], acc[mt][2 * p + 1][1]);
                    else
                        *reinterpret_cast<float4*>(d + p * 16) =
                            make_float4(acc[mt][2 * p][0], acc[mt][2 * p][1],
                                        acc[mt][2 * p + 1][0], acc[mt][2 * p + 1][1]);
                }
            }
            if (o2 < N_VOX) {
                float* d = H + (size_t)o2 * 64 + cq;
#pragma unroll
                for (int p = 0; p < 4; p++) {
                    if (SCATTER)
                        RED4(d + p * 16, acc[mt][2 * p][2], acc[mt][2 * p][3],
                                         acc[mt][2 * p + 1][2], acc[mt][2 * p + 1][3]);
                    else
                        *reinterpret_cast<float4*>(d + p * 16) =
                            make_float4(acc[mt][2 * p][2], acc[mt][2 * p][3],
                                        acc[mt][2 * p + 1][2], acc[mt][2 * p + 1][3]);
                }
            }
        }

        // advance pipeline
        myrow = nrow; myorow = norow; tfirst = nfirst;
    }
}

// ---------------------------------------------------------------------------
// W prep: fp16 [27][64 k'][72 n'] with:
//  - k PERMUTATION matching the contiguous-line gather: orig k<32 (line 0)
//    -> k' = 8*(k/4) + (k%4); orig k>=32 -> k' = 8*((k-32)/4) + 4 + (k-32)%4
//  - n INTERLEAVE within each 16-col block (p=n/16, pair=c/4, sub=c%4):
//    slot = p*16 + (sub<2 ? 2*pair+sub : 8+2*pair+(sub-2))
__global__ void wprep_kernel(const float* __restrict__ W)
{
    const int o = blockIdx.x;
    const int t = threadIdx.x;   // 128
    // zero padding columns once
    for (int idx = t; idx < 4608; idx += 128)
        if (idx % 72 >= 64) g_wh[(size_t)o * 4608 + idx] = __float2half(0.f);
    for (int idx = t; idx < 4096; idx += 128) {
        const int k = idx >> 6, n = idx & 63;
        int kp;
        if (k < 32) kp = 8 * (k >> 2) + (k & 3);
        else        kp = 8 * ((k - 32) >> 2) + 4 + ((k - 32) & 3);
        const int p = n >> 4, c = n & 15;
        const int pair = c >> 2, sub = c & 3;
        const int slot = p * 16 + ((sub < 2) ? (pair * 2 + sub)
                                             : (8 + pair * 2 + (sub - 2)));
        float v = W[(size_t)o * 4096 + k * 64 + n];
        g_wh[(size_t)o * 4608 + kp * 72 + slot] = __float2half(v);
    }
}

// ---------------------------------------------------------------------------
__global__ void zero_stats_kernel() { g_stats[threadIdx.x] = 0.f; }

// 2 independent row streams per thread (MLP=2), 2048 blocks
__global__ void stats_kernel(const float* __restrict__ h, int statoff)
{
    const int t = threadIdx.x;          // 256
    const int ch = t & 63;
    const int g  = t >> 6;
    const int stride = gridDim.x * 4;
    float s = 0.f, sq = 0.f;
    for (int row = blockIdx.x * 4 + g; row < N_VOX; row += stride * 2) {
        float v0 = h[(size_t)row * 64 + ch];
        const int row2 = row + stride;
        float v1 = (row2 < N_VOX) ? h[(size_t)row2 * 64 + ch] : 0.f;
        s += v0; sq = fmaf(v0, v0, sq);
        s += v1; sq = fmaf(v1, v1, sq);
    }
    __shared__ float sh[2][4][64];
    sh[0][g][ch] = s;
    sh[1][g][ch] = sq;
    __syncthreads();
    if (t < 64) {
        float ss = sh[0][0][t] + sh[0][1][t] + sh[0][2][t] + sh[0][3][t];
        atomicAdd(&g_stats[statoff + t], ss);
    } else if (t < 128) {
        int c = t - 64;
        float qq = sh[1][0][c] + sh[1][1][c] + sh[1][2][c] + sh[1][3][c];
        atomicAdd(&g_stats[statoff + 64 + c], qq);
    }
}

__global__ void finalize_stats_kernel(const float* __restrict__ gamma,
                                      const float* __restrict__ beta,
                                      int statoff, int coefoff)
{
    const int c = threadIdx.x;  // 64
    const float inv_n = 1.0f / (float)N_VOX;
    float mu  = g_stats[statoff + c] * inv_n;
    float var = g_stats[statoff + 64 + c] * inv_n - mu * mu;
    float sc  = gamma[c] * rsqrtf(var + EPSV);
    g_coef[coefoff + c]      = sc;
    g_coef[coefoff + 64 + c] = beta[c] - mu * sc;
}

// out = relu(bn2(h2) + x)
__global__ void final_kernel(const float* __restrict__ h2,
                             const float* __restrict__ x,
                             float* __restrict__ out, int coefoff)
{
    int kk = blockIdx.x * blockDim.x + threadIdx.x;
    if (kk >= N_VOX * 16) return;
    int cb = (kk & 15) * 4;
    float4 v = reinterpret_cast<const float4*>(h2)[kk];
    float4 r = reinterpret_cast<const float4*>(x)[kk];
    float s0 = g_coef[coefoff + cb + 0], b0 = g_coef[coefoff + 64 + cb + 0];
    float s1 = g_coef[coefoff + cb + 1], b1 = g_coef[coefoff + 64 + cb + 1];
    float s2 = g_coef[coefoff + cb + 2], b2 = g_coef[coefoff + 64 + cb + 2];
    float s3 = g_coef[coefoff + cb + 3], b3 = g_coef[coefoff + 64 + cb + 3];
    v.x = fmaxf(fmaf(v.x, s0, b0) + r.x, 0.f);
    v.y = fmaxf(fmaf(v.y, s1, b1) + r.y, 0.f);
    v.z = fmaxf(fmaf(v.z, s2, b2) + r.z, 0.f);
    v.w = fmaxf(fmaf(v.w, s3, b3) + r.w, 0.f);
    reinterpret_cast<float4*>(out)[kk] = v;
}

// ---------------------------------------------------------------------------
extern "C" void kernel_launch(void* const* d_in, const int* in_sizes, int n_in,
                              void* d_out, int out_size)
{
    const float* x      = (const float*)d_in[0];
    const float* W1     = (const float*)d_in[1];
    const float* gamma1 = (const float*)d_in[2];
    const float* beta1  = (const float*)d_in[3];
    const float* W2     = (const float*)d_in[4];
    const float* gamma2 = (const float*)d_in[5];
    const float* beta2  = (const float*)d_in[6];
    const int*   in_map = (const int*)d_in[7];
    const int*   out_map= (const int*)d_in[8];
    float*       out    = (float*)d_out;

    float* h1;  cudaGetSymbolAddress((void**)&h1, g_h1);
    float* h2;  cudaGetSymbolAddress((void**)&h2, g_h2);
    __half* wh; cudaGetSymbolAddress((void**)&wh, g_wh);

    const dim3 scat_grid(PP / (128 * TILES), 26);
    const int  center_blocks = (N_VOX + 128 * TILES - 1) / (128 * TILES);
    const int  ew_blocks     = (N_VOX * 16 + 255) / 256;

    zero_stats_kernel<<<1, 256>>>();

    // conv1 (raw x)
    wprep_kernel<<<27, 128>>>(W1);
    conv_mma_kernel<false, false><<<center_blocks, 128, DSMEM_BYTES>>>(x, wh, nullptr, nullptr, h1);
    conv_mma_kernel<true,  false><<<scat_grid,     128, DSMEM_BYTES>>>(x, wh, in_map, out_map, h1);
    stats_kernel<<<2048, 256>>>(h1, 0);
    finalize_stats_kernel<<<1, 64>>>(gamma1, beta1, 0, 0);

    // conv2: BN1+ReLU fused into the gather (h1 stays raw)
    wprep_kernel<<<27, 128>>>(W2);
    conv_mma_kernel<false, true><<<center_blocks, 128, DSMEM_BYTES>>>(h1, wh, nullptr, nullptr, h2);
    conv_mma_kernel<true,  true><<<scat_grid,     128, DSMEM_BYTES>>>(h1, wh, in_map, out_map, h2);
    stats_kernel<<<2048, 256>>>(h2, 128);
    finalize_stats_kernel<<<1, 64>>>(gamma2, beta2, 128, 128);

    // bn2 + residual + relu -> d_out
    final_kernel<<<ew_blocks, 256>>>(h2, x, out, 128);
}